// round 5
// baseline (speedup 1.0000x reference)
#include <cuda_runtime.h>

#define VOCAB 200000
#define EMBED 128
#define N_POS 10
#define N_NEG 64
#define N_SCORES (N_POS + N_NEG)      // 74
#define N_ROWS (1 + N_SCORES)         // 75

#define THREADS 1024
#define ELEMS_PER_BLOCK (THREADS * 16)                 // 16384 floats per block
#define BLOCKS_X ((VOCAB + ELEMS_PER_BLOCK - 1) / ELEMS_PER_BLOCK)  // 13
#define TOTAL_BLOCKS (BLOCKS_X * N_ROWS)               // 975

// Scratch (no allocation allowed): nonzero index per one-hot row.
// slot 0 = center, 1..10 = positives, 11..74 = negatives.
__device__ int g_idx[N_ROWS];
// Ticket counter for the last-block pattern. Zero at load; the last block
// resets it to 0 every call -> deterministic across graph replays.
__device__ unsigned int g_done;

__device__ __forceinline__ float log_sigmoid(float x) {
    // stable: min(x,0) - log1p(exp(-|x|))
    return fminf(x, 0.0f) - log1pf(__expf(-fabsf(x)));
}

__global__ void __launch_bounds__(THREADS)
skipgram_fused_kernel(const float* __restrict__ center,
                      const float* __restrict__ pos,
                      const float* __restrict__ neg,
                      const float* __restrict__ in_emb,   // [EMBED, VOCAB]
                      const float* __restrict__ out_emb,  // [VOCAB, EMBED]
                      float* __restrict__ out)
{
    const int tid  = threadIdx.x;
    const int row  = blockIdx.y;

    // ---- Phase 1: scan this block's chunk of the one-hot row ----------------
    const float* base;
    if (row == 0)            base = center;
    else if (row <= N_POS)   base = pos + (size_t)(row - 1) * VOCAB;
    else                     base = neg + (size_t)(row - 1 - N_POS) * VOCAB;

    const int blk_start = blockIdx.x * ELEMS_PER_BLOCK;
    #pragma unroll
    for (int c = 0; c < 4; c++) {
        const int i = blk_start + c * (THREADS * 4) + tid * 4;
        if (i < VOCAB) {  // VOCAB % 4 == 0 -> full float4 in bounds
            float4 v = *reinterpret_cast<const float4*>(base + i);
            if (v.x != 0.0f) g_idx[row] = i + 0;
            if (v.y != 0.0f) g_idx[row] = i + 1;
            if (v.z != 0.0f) g_idx[row] = i + 2;
            if (v.w != 0.0f) g_idx[row] = i + 3;
        }
    }

    // ---- Last-block handoff (cub pattern) ----------------------------------
    __syncthreads();                 // all block stores program-ordered before fence
    __shared__ bool am_last;
    if (tid == 0) {
        __threadfence();             // release: publish this block's g_idx writes
        unsigned int t = atomicAdd(&g_done, 1u);
        am_last = (t == TOTAL_BLOCKS - 1);
    }
    __syncthreads();
    if (!am_last) return;
    __threadfence();                 // acquire: see every block's g_idx writes

    // ---- Phase 2: 74 dot products + log-sigmoid reduction (last block) -----
    __shared__ int   sidx[N_ROWS];
    __shared__ float ctr[EMBED];
    __shared__ float wsum[32];

    if (tid < N_ROWS) sidx[tid] = g_idx[tid];   // 75 parallel L2 reads
    __syncthreads();
    const int c = sidx[0];
    if (tid < EMBED) ctr[tid] = in_emb[(size_t)tid * VOCAB + c];
    __syncthreads();

    const int warp = tid >> 5;
    const int lane = tid & 31;

    // Warp w handles scores w, w+32, w+64 with INDEPENDENT accumulators so
    // all gather loads issue concurrently (overlapped DRAM latency).
    float dot[3] = {0.0f, 0.0f, 0.0f};
    #pragma unroll
    for (int j = 0; j < 3; j++) {
        const int s = warp + 32 * j;
        if (s < N_SCORES) {
            const int idx = sidx[s + 1];
            if (s < N_POS) {
                #pragma unroll
                for (int k = lane; k < EMBED; k += 32)
                    dot[j] = fmaf(ctr[k], in_emb[(size_t)k * VOCAB + idx], dot[j]);
            } else {
                #pragma unroll
                for (int k = lane; k < EMBED; k += 32)
                    dot[j] = fmaf(ctr[k], out_emb[(size_t)idx * EMBED + k], dot[j]);
            }
        }
    }

    float local = 0.0f;
    #pragma unroll
    for (int j = 0; j < 3; j++) {
        const int s = warp + 32 * j;
        #pragma unroll
        for (int o = 16; o; o >>= 1)
            dot[j] += __shfl_xor_sync(0xFFFFFFFFu, dot[j], o);
        if (lane == 0 && s < N_SCORES)
            local += log_sigmoid((s < N_POS) ? dot[j] : -dot[j]);
    }

    if (lane == 0) wsum[warp] = local;
    __syncthreads();

    if (tid == 0) {
        float acc = 0.0f;
        #pragma unroll
        for (int w = 0; w < 32; w++) acc += wsum[w];
        out[0] = -acc;
        g_done = 0;                  // reset for next graph replay
    }
}

// ---------------------------------------------------------------------------
// Inputs (metadata order):
//   d_in[0] center_word        [200000]        f32
//   d_in[1] positive_words     [10, 200000]    f32
//   d_in[2] negative_words     [64, 200000]    f32
//   d_in[3] input_embeddings   [128, 200000]   f32
//   d_in[4] output_embeddings  [200000, 128]   f32
// d_out: 1 x f32 scalar loss
// ---------------------------------------------------------------------------
extern "C" void kernel_launch(void* const* d_in, const int* in_sizes, int n_in,
                              void* d_out, int out_size)
{
    const float* center = (const float*)d_in[0];
    const float* pos    = (const float*)d_in[1];
    const float* neg    = (const float*)d_in[2];
    const float* in_emb = (const float*)d_in[3];
    const float* ot_emb = (const float*)d_in[4];
    float* out          = (float*)d_out;

    dim3 grid(BLOCKS_X, N_ROWS);
    skipgram_fused_kernel<<<grid, THREADS>>>(center, pos, neg, in_emb, ot_emb, out);
}

// round 8
// speedup vs baseline: 1.1336x; 1.1336x over previous
#include <cuda_runtime.h>

#define VOCAB 200000
#define EMBED 128
#define N_POS 10
#define N_NEG 64
#define N_SCORES (N_POS + N_NEG)            // 74
#define N_ROWS (1 + N_SCORES)               // 75

#define THREADS 256
#define QPT 16                              // float4 quads per thread
#define QPB (THREADS * QPT)                 // 4096 quads per block
#define N_QUADS (VOCAB / 4)                 // 50000
#define BLOCKS_X ((N_QUADS + QPB - 1) / QPB)    // 13
#define TOTAL_BLOCKS (BLOCKS_X * N_ROWS)        // 975

// Scratch (no device allocation allowed). slot 0 = center, 1..10 = pos, 11..74 = neg.
__device__ int g_idx[N_ROWS];
// Ticket counter; last block resets it -> deterministic across graph replays.
__device__ unsigned int g_done;

__device__ __forceinline__ float log_sigmoid(float x) {
    return fminf(x, 0.0f) - log1pf(__expf(-fabsf(x)));   // stable
}

__device__ __forceinline__ void l2_prefetch(const void* p) {
    asm volatile("prefetch.global.L2 [%0];" :: "l"(p));
}

__global__ void __launch_bounds__(THREADS, 8)
skipgram_kernel(const float* __restrict__ center,
                const float* __restrict__ pos,
                const float* __restrict__ neg,
                const float* __restrict__ in_emb,    // [EMBED, VOCAB]
                const float* __restrict__ out_emb,   // [VOCAB, EMBED]
                float* __restrict__ out)
{
    const int tid = threadIdx.x;
    const int row = blockIdx.y;

    const float* base;
    if (row == 0)            base = center;
    else if (row <= N_POS)   base = pos + (size_t)(row - 1) * VOCAB;
    else                     base = neg + (size_t)(row - 1 - N_POS) * VOCAB;
    const float4* bq = reinterpret_cast<const float4*>(base);

    const int qbase = blockIdx.x * QPB;     // first quad of this block

    // ---- Scan: weighted-sum one-hot locate. acc = sum v * (rel+1), all FFMA-imm.
    // rel of quad (c, thread tid) component k = c*1024 + k   (elem base (qbase+tid)*4)
    float acc0 = 0.0f, acc1 = 0.0f;
    if (qbase + QPB <= N_QUADS) {
        // fast path: 4 batches of 4 fully-independent float4 loads, no tests between
        #pragma unroll
        for (int b = 0; b < 4; b++) {
            float4 v0 = bq[qbase + (b * 4 + 0) * THREADS + tid];
            float4 v1 = bq[qbase + (b * 4 + 1) * THREADS + tid];
            float4 v2 = bq[qbase + (b * 4 + 2) * THREADS + tid];
            float4 v3 = bq[qbase + (b * 4 + 3) * THREADS + tid];
            const float r0 = (float)((b * 4 + 0) * 1024 + 1);
            const float r1 = (float)((b * 4 + 1) * 1024 + 1);
            const float r2 = (float)((b * 4 + 2) * 1024 + 1);
            const float r3 = (float)((b * 4 + 3) * 1024 + 1);
            acc0 = fmaf(v0.x, r0 + 0.f, acc0); acc1 = fmaf(v0.y, r0 + 1.f, acc1);
            acc0 = fmaf(v0.z, r0 + 2.f, acc0); acc1 = fmaf(v0.w, r0 + 3.f, acc1);
            acc0 = fmaf(v1.x, r1 + 0.f, acc0); acc1 = fmaf(v1.y, r1 + 1.f, acc1);
            acc0 = fmaf(v1.z, r1 + 2.f, acc0); acc1 = fmaf(v1.w, r1 + 3.f, acc1);
            acc0 = fmaf(v2.x, r2 + 0.f, acc0); acc1 = fmaf(v2.y, r2 + 1.f, acc1);
            acc0 = fmaf(v2.z, r2 + 2.f, acc0); acc1 = fmaf(v2.w, r2 + 3.f, acc1);
            acc0 = fmaf(v3.x, r3 + 0.f, acc0); acc1 = fmaf(v3.y, r3 + 1.f, acc1);
            acc0 = fmaf(v3.z, r3 + 2.f, acc0); acc1 = fmaf(v3.w, r3 + 3.f, acc1);
        }
    } else {
        // tail block (one per row): per-quad guard
        #pragma unroll
        for (int c = 0; c < QPT; c++) {
            const int q = qbase + c * THREADS + tid;
            if (q < N_QUADS) {
                float4 v = bq[q];
                const float r = (float)(c * 1024 + 1);
                acc0 = fmaf(v.x, r + 0.f, acc0); acc1 = fmaf(v.y, r + 1.f, acc1);
                acc0 = fmaf(v.z, r + 2.f, acc0); acc1 = fmaf(v.w, r + 3.f, acc1);
            }
        }
    }

    const float acc = acc0 + acc1;
    if (acc != 0.0f) {                       // exactly one finder thread per row
        const int idx = (qbase + tid) * 4 + (int)acc - 1;
        g_idx[row] = idx;
        // warm L2 for the epilogue gather of this row
        if (row > N_POS) {                   // negative: contiguous 512B row
            const char* p = (const char*)(out_emb + (size_t)idx * EMBED);
            #pragma unroll
            for (int j = 0; j < 4; j++) l2_prefetch(p + j * 128);
        } else {                             // center/positive: strided column
            for (int k = 0; k < EMBED; k++)
                l2_prefetch(in_emb + (size_t)k * VOCAB + idx);
        }
    }

    // ---- Last-block handoff ----
    __syncthreads();
    __shared__ bool am_last;
    if (tid == 0) {
        __threadfence();
        am_last = (atomicAdd(&g_done, 1u) == TOTAL_BLOCKS - 1);
    }
    __syncthreads();
    if (!am_last) return;
    __threadfence();

    // ---- Epilogue: 74 dots + log-sigmoid (L2 is warm from prefetches) ----
    __shared__ int   sidx[N_ROWS];
    __shared__ float ctr[EMBED];
    __shared__ float wsum[8];

    if (tid < N_ROWS) sidx[tid] = g_idx[tid];
    __syncthreads();
    const int c = sidx[0];
    if (tid < EMBED) ctr[tid] = in_emb[(size_t)tid * VOCAB + c];
    __syncthreads();

    const int warp = tid >> 5;               // 0..7
    const int lane = tid & 31;

    float dot[10];
    #pragma unroll
    for (int j = 0; j < 10; j++) dot[j] = 0.0f;

    #pragma unroll
    for (int j = 0; j < 10; j++) {
        const int s = warp + 8 * j;
        if (s < N_SCORES) {
            const int idx = sidx[s + 1];
            if (s < N_POS) {
                #pragma unroll
                for (int k = lane; k < EMBED; k += 32)
                    dot[j] = fmaf(ctr[k], in_emb[(size_t)k * VOCAB + idx], dot[j]);
            } else {
                #pragma unroll
                for (int k = lane; k < EMBED; k += 32)
                    dot[j] = fmaf(ctr[k], out_emb[(size_t)idx * EMBED + k], dot[j]);
            }
        }
    }

    float local = 0.0f;
    #pragma unroll
    for (int j = 0; j < 10; j++) {
        const int s = warp + 8 * j;
        #pragma unroll
        for (int o = 16; o; o >>= 1)
            dot[j] += __shfl_xor_sync(0xFFFFFFFFu, dot[j], o);
        if (lane == 0 && s < N_SCORES)
            local += log_sigmoid((s < N_POS) ? dot[j] : -dot[j]);
    }

    if (lane == 0) wsum[warp] = local;
    __syncthreads();

    if (tid == 0) {
        float a = 0.0f;
        #pragma unroll
        for (int w = 0; w < 8; w++) a += wsum[w];
        out[0] = -a;
        g_done = 0;                          // reset for next replay
    }
}

// ---------------------------------------------------------------------------
// Inputs (metadata order):
//   d_in[0] center_word        [200000]        f32
//   d_in[1] positive_words     [10, 200000]    f32
//   d_in[2] negative_words     [64, 200000]    f32
//   d_in[3] input_embeddings   [128, 200000]   f32
//   d_in[4] output_embeddings  [200000, 128]   f32
// d_out: 1 x f32 scalar loss
// ---------------------------------------------------------------------------
extern "C" void kernel_launch(void* const* d_in, const int* in_sizes, int n_in,
                              void* d_out, int out_size)
{
    const float* center = (const float*)d_in[0];
    const float* pos    = (const float*)d_in[1];
    const float* neg    = (const float*)d_in[2];
    const float* in_emb = (const float*)d_in[3];
    const float* ot_emb = (const float*)d_in[4];
    float* out          = (float*)d_out;

    dim3 grid(BLOCKS_X, N_ROWS);
    skipgram_kernel<<<grid, THREADS>>>(center, pos, neg, in_emb, ot_emb, out);
}

// round 9
// speedup vs baseline: 1.1586x; 1.0220x over previous
#include <cuda_runtime.h>

#define VOCAB 200000
#define EMBED 128
#define N_POS 10
#define N_NEG 64
#define N_SCORES (N_POS + N_NEG)            // 74
#define N_ROWS (1 + N_SCORES)               // 75

#define THREADS 256
#define QPT 16                              // float4 quads per thread
#define QPB (THREADS * QPT)                 // 4096 quads per block
#define N_QUADS (VOCAB / 4)                 // 50000
#define BLOCKS_X ((N_QUADS + QPB - 1) / QPB)    // 13
#define TOTAL_BLOCKS (BLOCKS_X * N_ROWS)        // 975

// Scratch. slot 0 = center, 1..10 = pos, 11..74 = neg.
__device__ int g_idx[N_ROWS];
// Ticket counter; last block resets it -> deterministic across graph replays.
__device__ unsigned int g_done;

__device__ __forceinline__ float log_sigmoid(float x) {
    return fminf(x, 0.0f) - log1pf(__expf(-fabsf(x)));   // stable
}

__device__ __forceinline__ void l2_prefetch(const void* p) {
    asm volatile("prefetch.global.L2 [%0];" :: "l"(p));
}

__global__ void __launch_bounds__(THREADS, 5)
skipgram_kernel(const float* __restrict__ center,
                const float* __restrict__ pos,
                const float* __restrict__ neg,
                const float* __restrict__ in_emb,    // [EMBED, VOCAB]
                const float* __restrict__ out_emb,   // [VOCAB, EMBED]
                float* __restrict__ out)
{
    const int tid = threadIdx.x;
    const int row = blockIdx.y;

    const float* base;
    if (row == 0)            base = center;
    else if (row <= N_POS)   base = pos + (size_t)(row - 1) * VOCAB;
    else                     base = neg + (size_t)(row - 1 - N_POS) * VOCAB;

    const int qbase = blockIdx.x * QPB;     // first quad of this block
    // thread base: chunk c lives at tb[c * THREADS] -> constant 4KB immediate offsets
    const float4* tb = reinterpret_cast<const float4*>(base) + qbase + tid;

    // ---- Scan: weighted-sum one-hot locate, 8 loads in flight throughout.
    // acc = sum v * (c*1024 + k + 1); exact since one-hot values are exactly 1.0/0.0.
    float acc0 = 0.0f, acc1 = 0.0f;
    if (qbase + QPB <= N_QUADS) {
        float4 v[8];
        #pragma unroll
        for (int c = 0; c < 8; c++) v[c] = tb[c * THREADS];          // chunks 0-7
        #pragma unroll
        for (int c = 0; c < 8; c++) {
            const float4 cur = v[c];
            v[c] = tb[(c + 8) * THREADS];                            // issue chunk c+8
            const float r = (float)(c * 1024 + 1);
            acc0 = fmaf(cur.x, r,        acc0);
            acc1 = fmaf(cur.y, r + 1.0f, acc1);
            acc0 = fmaf(cur.z, r + 2.0f, acc0);
            acc1 = fmaf(cur.w, r + 3.0f, acc1);
        }
        #pragma unroll
        for (int c = 0; c < 8; c++) {                                // drain chunks 8-15
            const float r = (float)((c + 8) * 1024 + 1);
            acc0 = fmaf(v[c].x, r,        acc0);
            acc1 = fmaf(v[c].y, r + 1.0f, acc1);
            acc0 = fmaf(v[c].z, r + 2.0f, acc0);
            acc1 = fmaf(v[c].w, r + 3.0f, acc1);
        }
    } else {
        // tail block (one per row): per-quad guard
        #pragma unroll
        for (int c = 0; c < QPT; c++) {
            const int q = qbase + c * THREADS + tid;
            if (q < N_QUADS) {
                float4 v = tb[c * THREADS];
                const float r = (float)(c * 1024 + 1);
                acc0 = fmaf(v.x, r,        acc0);
                acc1 = fmaf(v.y, r + 1.0f, acc1);
                acc0 = fmaf(v.z, r + 2.0f, acc0);
                acc1 = fmaf(v.w, r + 3.0f, acc1);
            }
        }
    }

    const float acc = acc0 + acc1;
    if (acc != 0.0f) {                       // exactly one finder thread per row
        const int idx = (qbase + tid) * 4 + (int)acc - 1;
        g_idx[row] = idx;
        // warm L2 for the epilogue gather of this row
        if (row > N_POS) {                   // negative: contiguous 512B row
            const char* p = (const char*)(out_emb + (size_t)idx * EMBED);
            #pragma unroll
            for (int j = 0; j < 4; j++) l2_prefetch(p + j * 128);
        } else {                             // center/positive: strided column
            for (int k = 0; k < EMBED; k++)
                l2_prefetch(in_emb + (size_t)k * VOCAB + idx);
        }
    }

    // ---- Last-block handoff ----
    __syncthreads();
    __shared__ bool am_last;
    if (tid == 0) {
        __threadfence();
        am_last = (atomicAdd(&g_done, 1u) == TOTAL_BLOCKS - 1);
    }
    __syncthreads();
    if (!am_last) return;
    __threadfence();

    // ---- Epilogue: 74 dots + log-sigmoid (L2 warm from prefetches) ----
    __shared__ int   sidx[N_ROWS];
    __shared__ float ctr[EMBED];
    __shared__ float wsum[8];

    if (tid < N_ROWS) sidx[tid] = g_idx[tid];
    __syncthreads();
    const int c = sidx[0];
    if (tid < EMBED) ctr[tid] = in_emb[(size_t)tid * VOCAB + c];
    __syncthreads();

    const int warp = tid >> 5;               // 0..7
    const int lane = tid & 31;

    float dot[10];
    #pragma unroll
    for (int j = 0; j < 10; j++) dot[j] = 0.0f;

    #pragma unroll
    for (int j = 0; j < 10; j++) {
        const int s = warp + 8 * j;
        if (s < N_SCORES) {
            const int idx = sidx[s + 1];
            if (s < N_POS) {
                #pragma unroll
                for (int k = lane; k < EMBED; k += 32)
                    dot[j] = fmaf(ctr[k], in_emb[(size_t)k * VOCAB + idx], dot[j]);
            } else {
                #pragma unroll
                for (int k = lane; k < EMBED; k += 32)
                    dot[j] = fmaf(ctr[k], out_emb[(size_t)idx * EMBED + k], dot[j]);
            }
        }
    }

    float local = 0.0f;
    #pragma unroll
    for (int j = 0; j < 10; j++) {
        const int s = warp + 8 * j;
        #pragma unroll
        for (int o = 16; o; o >>= 1)
            dot[j] += __shfl_xor_sync(0xFFFFFFFFu, dot[j], o);
        if (lane == 0 && s < N_SCORES)
            local += log_sigmoid((s < N_POS) ? dot[j] : -dot[j]);
    }

    if (lane == 0) wsum[warp] = local;
    __syncthreads();

    if (tid == 0) {
        float a = 0.0f;
        #pragma unroll
        for (int w = 0; w < 8; w++) a += wsum[w];
        out[0] = -a;
        g_done = 0;                          // reset for next replay
    }
}

// ---------------------------------------------------------------------------
// Inputs (metadata order):
//   d_in[0] center_word        [200000]        f32
//   d_in[1] positive_words     [10, 200000]    f32
//   d_in[2] negative_words     [64, 200000]    f32
//   d_in[3] input_embeddings   [128, 200000]   f32
//   d_in[4] output_embeddings  [200000, 128]   f32
// d_out: 1 x f32 scalar loss
// ---------------------------------------------------------------------------
extern "C" void kernel_launch(void* const* d_in, const int* in_sizes, int n_in,
                              void* d_out, int out_size)
{
    const float* center = (const float*)d_in[0];
    const float* pos    = (const float*)d_in[1];
    const float* neg    = (const float*)d_in[2];
    const float* in_emb = (const float*)d_in[3];
    const float* ot_emb = (const float*)d_in[4];
    float* out          = (float*)d_out;

    dim3 grid(BLOCKS_X, N_ROWS);
    skipgram_kernel<<<grid, THREADS>>>(center, pos, neg, in_emb, ot_emb, out);
}

// round 13
// speedup vs baseline: 1.2861x; 1.1100x over previous
#include <cuda_runtime.h>

#define VOCAB 200000
#define EMBED 128
#define N_POS 10
#define N_NEG 64
#define N_SCORES (N_POS + N_NEG)            // 74
#define N_ROWS (1 + N_SCORES)               // 75

#define THREADS 256
#define QPT 25                              // float4 quads per thread
#define QPB (THREADS * QPT)                 // 6400 quads per block
#define N_QUADS (VOCAB / 4)                 // 50000
#define BLOCKS_X ((N_QUADS + QPB - 1) / QPB)    // 8
#define TOTAL_BLOCKS (BLOCKS_X * N_ROWS)        // 600  (single wave: <= 5*152 resident)
#define DEPTH 8                             // loads in flight per thread
#define STEADY (QPT - DEPTH)                // 17

// Scratch. slot 0 = center, 1..10 = pos, 11..74 = neg.
__device__ int g_idx[N_ROWS];
// Ticket counter; last block resets it -> deterministic across graph replays.
__device__ unsigned int g_done;

__device__ __forceinline__ float log_sigmoid(float x) {
    return fminf(x, 0.0f) - log1pf(__expf(-fabsf(x)));   // stable
}

__device__ __forceinline__ void l2_prefetch(const void* p) {
    asm volatile("prefetch.global.L2 [%0];" :: "l"(p));
}

__device__ __forceinline__ float4 ld_or_zero(const float4* p, bool ok) {
    float4 r = make_float4(0.f, 0.f, 0.f, 0.f);
    if (ok) r = *p;                          // predicated LDG.128 — stays async
    return r;
}

__global__ void __launch_bounds__(THREADS, 5)
skipgram_kernel(const float* __restrict__ center,
                const float* __restrict__ pos,
                const float* __restrict__ neg,
                const float* __restrict__ in_emb,    // [EMBED, VOCAB]
                const float* __restrict__ out_emb,   // [VOCAB, EMBED]
                float* __restrict__ out)
{
    const int tid = threadIdx.x;
    const int row = blockIdx.y;

    const float* base;
    if (row == 0)            base = center;
    else if (row <= N_POS)   base = pos + (size_t)(row - 1) * VOCAB;
    else                     base = neg + (size_t)(row - 1 - N_POS) * VOCAB;

    const int qbase = blockIdx.x * QPB;     // first quad of this block
    const int q0    = qbase + tid;          // quad index of chunk 0 for this thread
    const float4* tb = reinterpret_cast<const float4*>(base) + q0;

    // ---- Scan: weighted-sum one-hot locate; DEPTH loads in flight throughout.
    // acc = sum v * (c*1024 + k + 1); exact (one-hot entries are exactly 1.0/0.0,
    // zeros contribute exact +0.0 -> order-independent, weights < 2^24).
    float acc0 = 0.0f, acc1 = 0.0f;
    float4 v[DEPTH];

    #pragma unroll
    for (int c = 0; c < DEPTH; c++)
        v[c] = ld_or_zero(tb + c * THREADS, q0 + c * THREADS < N_QUADS);

    #pragma unroll
    for (int c = 0; c < STEADY; c++) {
        const float4 cur = v[c & (DEPTH - 1)];
        v[c & (DEPTH - 1)] =
            ld_or_zero(tb + (c + DEPTH) * THREADS, q0 + (c + DEPTH) * THREADS < N_QUADS);
        const float r = (float)(c * 1024 + 1);
        acc0 = fmaf(cur.x, r,        acc0);
        acc1 = fmaf(cur.y, r + 1.0f, acc1);
        acc0 = fmaf(cur.z, r + 2.0f, acc0);
        acc1 = fmaf(cur.w, r + 3.0f, acc1);
    }

    #pragma unroll
    for (int c = STEADY; c < QPT; c++) {     // drain
        const float4 cur = v[c & (DEPTH - 1)];
        const float r = (float)(c * 1024 + 1);
        acc0 = fmaf(cur.x, r,        acc0);
        acc1 = fmaf(cur.y, r + 1.0f, acc1);
        acc0 = fmaf(cur.z, r + 2.0f, acc0);
        acc1 = fmaf(cur.w, r + 3.0f, acc1);
    }

    const float acc = acc0 + acc1;
    if (acc != 0.0f) {                       // exactly one finder thread per row
        const int idx = q0 * 4 + (int)acc - 1;
        g_idx[row] = idx;
        // warm L2 for the epilogue gather of this row
        if (row > N_POS) {                   // negative: contiguous 512B row
            const char* p = (const char*)(out_emb + (size_t)idx * EMBED);
            #pragma unroll
            for (int j = 0; j < 4; j++) l2_prefetch(p + j * 128);
        } else {                             // center/positive: strided column
            for (int k = 0; k < EMBED; k++)
                l2_prefetch(in_emb + (size_t)k * VOCAB + idx);
        }
    }

    // ---- Last-block handoff ----
    __syncthreads();
    __shared__ bool am_last;
    if (tid == 0) {
        __threadfence();
        am_last = (atomicAdd(&g_done, 1u) == TOTAL_BLOCKS - 1);
    }
    __syncthreads();
    if (!am_last) return;
    __threadfence();

    // ---- Epilogue: 74 dots + log-sigmoid (L2 warm from prefetches) ----
    __shared__ int   sidx[N_ROWS];
    __shared__ float ctr[EMBED];
    __shared__ float wsum[8];

    if (tid < N_ROWS) sidx[tid] = g_idx[tid];
    __syncthreads();
    const int c = sidx[0];
    if (tid < EMBED) ctr[tid] = in_emb[(size_t)tid * VOCAB + c];
    __syncthreads();

    const int warp = tid >> 5;               // 0..7
    const int lane = tid & 31;

    float dot[10];
    #pragma unroll
    for (int j = 0; j < 10; j++) dot[j] = 0.0f;

    #pragma unroll
    for (int j = 0; j < 10; j++) {
        const int s = warp + 8 * j;
        if (s < N_SCORES) {
            const int idx = sidx[s + 1];
            if (s < N_POS) {
                #pragma unroll
                for (int k = lane; k < EMBED; k += 32)
                    dot[j] = fmaf(ctr[k], in_emb[(size_t)k * VOCAB + idx], dot[j]);
            } else {
                #pragma unroll
                for (int k = lane; k < EMBED; k += 32)
                    dot[j] = fmaf(ctr[k], out_emb[(size_t)idx * EMBED + k], dot[j]);
            }
        }
    }

    float local = 0.0f;
    #pragma unroll
    for (int j = 0; j < 10; j++) {
        const int s = warp + 8 * j;
        #pragma unroll
        for (int o = 16; o; o >>= 1)
            dot[j] += __shfl_xor_sync(0xFFFFFFFFu, dot[j], o);
        if (lane == 0 && s < N_SCORES)
            local += log_sigmoid((s < N_POS) ? dot[j] : -dot[j]);
    }

    if (lane == 0) wsum[warp] = local;
    __syncthreads();

    if (tid == 0) {
        float a = 0.0f;
        #pragma unroll
        for (int w = 0; w < 8; w++) a += wsum[w];
        out[0] = -a;
        g_done = 0;                          // reset for next replay
    }
}

// ---------------------------------------------------------------------------
// Inputs (metadata order):
//   d_in[0] center_word        [200000]        f32
//   d_in[1] positive_words     [10, 200000]    f32
//   d_in[2] negative_words     [64, 200000]    f32
//   d_in[3] input_embeddings   [128, 200000]   f32
//   d_in[4] output_embeddings  [200000, 128]   f32
// d_out: 1 x f32 scalar loss
// ---------------------------------------------------------------------------
extern "C" void kernel_launch(void* const* d_in, const int* in_sizes, int n_in,
                              void* d_out, int out_size)
{
    const float* center = (const float*)d_in[0];
    const float* pos    = (const float*)d_in[1];
    const float* neg    = (const float*)d_in[2];
    const float* in_emb = (const float*)d_in[3];
    const float* ot_emb = (const float*)d_in[4];
    float* out          = (float*)d_out;

    dim3 grid(BLOCKS_X, N_ROWS);
    skipgram_kernel<<<grid, THREADS>>>(center, pos, neg, in_emb, ot_emb, out);
}